// round 4
// baseline (speedup 1.0000x reference)
#include <cuda_runtime.h>
#include <cstdint>

// COO SpMM: out[dst] += val * x[src],  N=100K, E=1.6M, D=64.
//
// Fixed-stride bucketing (no hist/scan):
//   1. memset per-node counters (400KB)
//   2. scatter: pos = atomicAdd(cnt[dst]); bucket[dst*32+pos] = {src,val}
//      8 edges/thread, atomics batched for MLP. Overflow -> side list.
//   3. main: one warp per node, register accumulation, coalesced row store
//   4. fixup: RED.128 atomic adds for overflow entries (expected ~16 edges)

static constexpr int D_FEAT = 64;
static constexpr int MAX_N  = 100000;
static constexpr int SLOTS  = 32;      // Poisson(16): E[overflow edges] ~ 16 total
static constexpr int OCAP   = 8192;    // overflow list capacity
static constexpr int EPT    = 8;       // edges per scatter thread

// Scratch (allocation-free __device__ globals)
__device__ int  g_cnt[MAX_N + 1];            // [MAX_N] = overflow counter
__device__ int2 g_bucket[MAX_N * SLOTS];     // {src, float_as_int(val)}  (25.6 MB)
__device__ int4 g_over[OCAP];                // {src, dst, valbits, 0}

// ---------------- phase 1: scatter into fixed buckets ----------------

__global__ void __launch_bounds__(256) scatter_kernel(
    const int*   __restrict__ edge_src,
    const int*   __restrict__ edge_dst,
    const float* __restrict__ edge_val,
    int n_edges)
{
    int i = blockIdx.x * blockDim.x + threadIdx.x;
    int e0 = i * EPT;

    if (e0 + EPT - 1 < n_edges) {
        // vector loads: 2x int4 each
        int4 s0 = __ldg(reinterpret_cast<const int4*>(edge_src) + i * 2 + 0);
        int4 s1 = __ldg(reinterpret_cast<const int4*>(edge_src) + i * 2 + 1);
        int4 d0 = __ldg(reinterpret_cast<const int4*>(edge_dst) + i * 2 + 0);
        int4 d1 = __ldg(reinterpret_cast<const int4*>(edge_dst) + i * 2 + 1);
        int4 v0 = __ldg(reinterpret_cast<const int4*>(edge_val) + i * 2 + 0);
        int4 v1 = __ldg(reinterpret_cast<const int4*>(edge_val) + i * 2 + 1);

        int src[EPT] = {s0.x, s0.y, s0.z, s0.w, s1.x, s1.y, s1.z, s1.w};
        int dst[EPT] = {d0.x, d0.y, d0.z, d0.w, d1.x, d1.y, d1.z, d1.w};
        int val[EPT] = {v0.x, v0.y, v0.z, v0.w, v1.x, v1.y, v1.z, v1.w};

        // batch the return-atomics: 8 independent ATOMGs in flight
        int pos[EPT];
        #pragma unroll
        for (int k = 0; k < EPT; k++)
            pos[k] = atomicAdd(&g_cnt[dst[k]], 1);

        #pragma unroll
        for (int k = 0; k < EPT; k++) {
            if (pos[k] < SLOTS) {
                g_bucket[(size_t)dst[k] * SLOTS + pos[k]] =
                    make_int2(src[k], val[k]);
            } else {
                int o = atomicAdd(&g_cnt[MAX_N], 1);
                if (o < OCAP) g_over[o] = make_int4(src[k], dst[k], val[k], 0);
            }
        }
    } else {
        for (int e = e0; e < n_edges; e++) {
            int  dst = __ldg(edge_dst + e);
            int  pos = atomicAdd(&g_cnt[dst], 1);
            int  src = __ldg(edge_src + e);
            int  val = __float_as_int(__ldg(edge_val + e));
            if (pos < SLOTS) {
                g_bucket[(size_t)dst * SLOTS + pos] = make_int2(src, val);
            } else {
                int o = atomicAdd(&g_cnt[MAX_N], 1);
                if (o < OCAP) g_over[o] = make_int4(src, dst, val, 0);
            }
        }
    }
}

// ---------------- phase 2: accumulate, one warp per node ----------------

__global__ void __launch_bounds__(256) spmm_csr_kernel(
    const float* __restrict__ x,
    float*       __restrict__ out,
    int n_nodes)
{
    int wid  = (blockIdx.x * blockDim.x + threadIdx.x) >> 5;
    int lane = threadIdx.x & 31;
    if (wid >= n_nodes) return;

    int cnt = g_cnt[wid];
    if (cnt > SLOTS) cnt = SLOTS;
    const int2* bucket = g_bucket + (size_t)wid * SLOTS;

    const float2* xf2 = reinterpret_cast<const float2*>(x);
    float2 acc = make_float2(0.f, 0.f);

    int i = 0;
    for (; i + 3 < cnt; i += 4) {
        int2 p0 = __ldg(bucket + i + 0);
        int2 p1 = __ldg(bucket + i + 1);
        int2 p2 = __ldg(bucket + i + 2);
        int2 p3 = __ldg(bucket + i + 3);
        float2 v0 = __ldg(xf2 + (size_t)p0.x * 32 + lane);
        float2 v1 = __ldg(xf2 + (size_t)p1.x * 32 + lane);
        float2 v2 = __ldg(xf2 + (size_t)p2.x * 32 + lane);
        float2 v3 = __ldg(xf2 + (size_t)p3.x * 32 + lane);
        float s0 = __int_as_float(p0.y);
        float s1 = __int_as_float(p1.y);
        float s2 = __int_as_float(p2.y);
        float s3 = __int_as_float(p3.y);
        acc.x += v0.x * s0; acc.y += v0.y * s0;
        acc.x += v1.x * s1; acc.y += v1.y * s1;
        acc.x += v2.x * s2; acc.y += v2.y * s2;
        acc.x += v3.x * s3; acc.y += v3.y * s3;
    }
    for (; i < cnt; i++) {
        int2 p = __ldg(bucket + i);
        float2 v = __ldg(xf2 + (size_t)p.x * 32 + lane);
        float s = __int_as_float(p.y);
        acc.x += v.x * s; acc.y += v.y * s;
    }

    reinterpret_cast<float2*>(out)[(size_t)wid * 32 + lane] = acc;
}

// ---------------- phase 3: overflow fixup (normally ~16 edges) ----------------

__global__ void __launch_bounds__(256) fixup_kernel(
    const float* __restrict__ x,
    float*       __restrict__ out)
{
    int t = blockIdx.x * blockDim.x + threadIdx.x;
    int e = t >> 4;
    int c = t & 15;
    int ocnt = g_cnt[MAX_N];
    if (ocnt > OCAP) ocnt = OCAP;
    if (e >= ocnt) return;

    int4 rec = g_over[e];
    float val = __int_as_float(rec.z);
    float4 v = __ldg(reinterpret_cast<const float4*>(x + (size_t)rec.x * D_FEAT) + c);
    float4 r;
    r.x = v.x * val; r.y = v.y * val; r.z = v.z * val; r.w = v.w * val;
    float* o = out + (size_t)rec.y * D_FEAT + c * 4;
    asm volatile("red.global.add.v4.f32 [%0], {%1, %2, %3, %4};"
                 :: "l"(o), "f"(r.x), "f"(r.y), "f"(r.z), "f"(r.w)
                 : "memory");
}

// ---------------- launch ----------------

extern "C" void kernel_launch(void* const* d_in, const int* in_sizes, int n_in,
                              void* d_out, int out_size) {
    const float* x        = (const float*)d_in[0];
    const float* edge_val = (const float*)d_in[1];
    const int*   edge_src = (const int*)d_in[2];
    const int*   edge_dst = (const int*)d_in[3];
    float*       out      = (float*)d_out;

    int n_edges = in_sizes[1];
    int n_nodes = out_size / D_FEAT;

    void* cnt_ptr = nullptr;
    cudaGetSymbolAddress(&cnt_ptr, g_cnt);
    cudaMemsetAsync(cnt_ptr, 0, (MAX_N + 1) * sizeof(int), 0);

    int sc_threads = (n_edges + EPT - 1) / EPT;
    scatter_kernel<<<(sc_threads + 255) / 256, 256>>>(edge_src, edge_dst,
                                                      edge_val, n_edges);

    int warps_per_block = 256 / 32;
    int grid = (n_nodes + warps_per_block - 1) / warps_per_block;
    spmm_csr_kernel<<<grid, 256>>>(x, out, n_nodes);

    fixup_kernel<<<(OCAP * 16) / 256, 256>>>(x, out);
}